// round 13
// baseline (speedup 1.0000x reference)
#include <cuda_runtime.h>
#include <cuda_fp16.h>
#include <cstdint>

#define NTOK 2048
#define DIM  512
#define NMOM 13
#define NCOEF (2*NMOM)

// ---------------- scratch (device globals: allocation-free) ----------------
__device__ __half g_hh [NTOK*DIM];
__device__ __half g_Oh [NTOK*DIM];
__device__ __half g_wqh[DIM*DIM];
__device__ __half g_wkh[DIM*DIM];
__device__ __half g_wvh[DIM*DIM];
__device__ __half g_woh[DIM*DIM];
__device__ float g_Q[NTOK*DIM], g_K[NTOK*DIM], g_V[NTOK*DIM];

// ---------------- PTX helpers ----------------
__device__ __forceinline__ uint32_t smem_u32(const void* p) {
    uint32_t a;
    asm("{ .reg .u64 t; cvta.to.shared.u64 t, %1; cvt.u32.u64 %0, t; }" : "=r"(a) : "l"(p));
    return a;
}
__device__ __forceinline__ void cpa16(uint32_t sdst, const void* gsrc) {
    asm volatile("cp.async.cg.shared.global [%0], [%1], 16;\n" :: "r"(sdst), "l"(gsrc));
}
#define CP_COMMIT() asm volatile("cp.async.commit_group;\n" ::: "memory")
#define CP_WAIT(n)  asm volatile("cp.async.wait_group %0;\n" :: "n"(n) : "memory")

__device__ __forceinline__ void ldsm4(uint32_t* r, uint32_t addr) {
    asm volatile("ldmatrix.sync.aligned.m8n8.x4.shared.b16 {%0,%1,%2,%3}, [%4];"
        : "=r"(r[0]), "=r"(r[1]), "=r"(r[2]), "=r"(r[3]) : "r"(addr));
}
__device__ __forceinline__ void mma_f16(float* c, const uint32_t* a,
                                        uint32_t b0, uint32_t b1) {
    asm volatile(
        "mma.sync.aligned.m16n8k16.row.col.f32.f16.f16.f32 "
        "{%0,%1,%2,%3}, {%4,%5,%6,%7}, {%8,%9}, {%0,%1,%2,%3};"
        : "+f"(c[0]), "+f"(c[1]), "+f"(c[2]), "+f"(c[3])
        : "r"(a[0]), "r"(a[1]), "r"(a[2]), "r"(a[3]), "r"(b0), "r"(b1));
}

// ---------------------------------------------------------------------------
// fp16 GEMM tile, NST-stage cp.async pipeline.  C[m,n] = sum_k A[m,k]*B[n,k].
// 256 threads, warps 2(m) x 4(n); BM in {64,128}, BN = 128; K = kIters*64.
// ---------------------------------------------------------------------------
template<int BM, int BN>
__device__ __forceinline__ void gemm_fill(uint32_t base,
    const __half* A, const __half* B, int k0, int tid)
{
#pragma unroll
    for (int i = 0; i < BM / 32; i++) {
        const int idx = i * 256 + tid;
        const int r = idx >> 3, u = idx & 7;
        cpa16(base + r * 128 + ((u ^ (r & 7)) << 4),
              A + (size_t)r * DIM + k0 + u * 8);
    }
#pragma unroll
    for (int i = 0; i < BN / 32; i++) {
        const int idx = i * 256 + tid;
        const int r = idx >> 3, u = idx & 7;
        cpa16(base + BM * 128 + r * 128 + ((u ^ (r & 7)) << 4),
              B + (size_t)r * DIM + k0 + u * 8);
    }
}

template<int BM, int BN, int NST>
__device__ void gemm_tile(const __half* __restrict__ A,
                          const __half* __restrict__ B,
                          float* __restrict__ C,
                          int mBase, int nBase, int kIters)
{
    constexpr int MT  = BM / 32;
    constexpr int BT  = BN / 64;
    constexpr int NTT = BN / 32;
    constexpr int STG = (BM + BN) * 128;

    extern __shared__ __align__(1024) char smem[];
    const uint32_t sb = smem_u32(smem);
    const int tid = threadIdx.x, lane = tid & 31, wid = tid >> 5;
    const int wm = wid >> 2, wn = wid & 3;

    const __half* Ab = A + (size_t)mBase * DIM;
    const __half* Bb = B + (size_t)nBase * DIM;

    float acc[MT][NTT][4];
#pragma unroll
    for (int i = 0; i < MT; i++)
#pragma unroll
        for (int j = 0; j < NTT; j++)
#pragma unroll
            for (int q = 0; q < 4; q++) acc[i][j][q] = 0.f;

    // Prologue: fill stages 0..NST-2.
#pragma unroll
    for (int s = 0; s < NST - 1; s++) {
        gemm_fill<BM, BN>(sb + s * STG, Ab, Bb, s * 64, tid);
        CP_COMMIT();
    }

    const int lrow = lane & 15, lhi = lane >> 4;

    int stage = 0, fstage = NST - 1;
    for (int it = 0; it < kIters; ++it) {
        CP_WAIT(NST - 2);         // fill(it) complete
        __syncthreads();
        if (it + NST - 1 < kIters)
            gemm_fill<BM, BN>(sb + fstage * STG, Ab, Bb, (it + NST - 1) * 64, tid);
        CP_COMMIT();              // possibly-empty group keeps wait count honest

        const uint32_t base = sb + stage * STG;
#pragma unroll
        for (int ks = 0; ks < 4; ks++) {
            const int u = ks * 2 + lhi;
            uint32_t a[MT][4], b[BT][4];
#pragma unroll
            for (int mt = 0; mt < MT; mt++) {
                const int r = wm * (BM / 2) + mt * 16 + lrow;
                ldsm4(a[mt], base + r * 128 + ((u ^ (r & 7)) << 4));
            }
#pragma unroll
            for (int bt = 0; bt < BT; bt++) {
                const int r = wn * (BN / 4) + bt * 16 + lrow;
                ldsm4(b[bt], base + BM * 128 + r * 128 + ((u ^ (r & 7)) << 4));
            }
#pragma unroll
            for (int mt = 0; mt < MT; mt++)
#pragma unroll
                for (int nt = 0; nt < NTT; nt++) {
                    const uint32_t b0 = (nt & 1) ? b[nt >> 1][1] : b[nt >> 1][0];
                    const uint32_t b1 = (nt & 1) ? b[nt >> 1][3] : b[nt >> 1][2];
                    mma_f16(acc[mt][nt], a[mt], b0, b1);
                }
        }
        stage  = (stage  == NST - 1) ? 0 : stage + 1;
        fstage = (fstage == NST - 1) ? 0 : fstage + 1;
    }

    const int crow = mBase + wm * (BM / 2) + (lane >> 2);
    const int ccol = nBase + wn * (BN / 4) + (lane & 3) * 2;
#pragma unroll
    for (int mt = 0; mt < MT; mt++)
#pragma unroll
        for (int nt = 0; nt < NTT; nt++) {
            float* p0 = C + (size_t)(crow + mt * 16) * DIM + ccol + nt * 8;
            float* p1 = p0 + 8 * DIM;
            *(float2*)p0 = make_float2(acc[mt][nt][0], acc[mt][nt][1]);
            *(float2*)p1 = make_float2(acc[mt][nt][2], acc[mt][nt][3]);
        }
}

// QKV: 192 CTAs (3 matrices x 16 m-tiles x 4 n-tiles), BM=128 BN=128,
// 3-stage (96KB).  Fat tiles halve L2 traffic (73MB -> 49MB).
__global__ void __launch_bounds__(256, 2)
qkv_gemm()
{
    const int j = blockIdx.x;
    const int which = j >> 6, t = j & 63;
    const __half* B = (which == 0) ? g_wqh : (which == 1) ? g_wkh : g_wvh;
    float*       C  = (which == 0) ? g_Q   : (which == 1) ? g_K   : g_V;
    gemm_tile<128, 128, 3>(g_hh, B, C, (t >> 2) * 128, (t & 3) * 128, 8);
}

// out: 128 CTAs (32 m-tiles x 4 n-tiles), BM=64 BN=128, 4-stage (96KB).
// Single wave: ~1 CTA/SM, deep pipeline hides per-iter latency.
__global__ void __launch_bounds__(256, 2)
out_gemm(float* __restrict__ out)
{
    const int t = blockIdx.x;
    gemm_tile<64, 128, 4>(g_Oh, g_woh, out, (t >> 2) * 64, (t & 3) * 128, 8);
}

// ---------------- fp32 -> fp16 convert (vectorized) -------------------------
__global__ void __launch_bounds__(256)
split_kernel(const float* __restrict__ h,  const float* __restrict__ wq,
             const float* __restrict__ wk, const float* __restrict__ wv,
             const float* __restrict__ wo)
{
    const int i = blockIdx.x * 256 + threadIdx.x;   // vec4 index
    const float4* src; __half* dst; int off;
    if (i < 262144) { src = (const float4*)h; dst = g_hh; off = i; }
    else {
        const int j = i - 262144;
        const int w = j >> 16;
        off = j & 65535;
        src = (const float4*)((w == 0) ? wq : (w == 1) ? wk : (w == 2) ? wv : wo);
        dst = (w == 0) ? g_wqh : (w == 1) ? g_wkh : (w == 2) ? g_wvh : g_woh;
    }
    const float4 x = src[off];
    __half2* d = (__half2*)(dst + (size_t)off * 4);
    d[0] = __floats2half2_rn(x.x, x.y);
    d[1] = __floats2half2_rn(x.z, x.w);
}

// ---------------------------------------------------------------------------
// Fused moments + apply.  Block per token, 256 threads (8 warps).
// ---------------------------------------------------------------------------
__device__ __constant__ float c_invfact[NMOM] = {
    1.0f, 1.0f, 0.5f, 1.6666667e-1f, 4.1666668e-2f, 8.3333338e-3f,
    1.3888889e-3f, 1.9841270e-4f, 2.4801588e-5f, 2.7557319e-6f,
    2.7557319e-7f, 2.5052108e-8f, 2.0876757e-9f };

__global__ void __launch_bounds__(256)
ma_kernel()
{
    const int n    = blockIdx.x;
    const int tid  = threadIdx.x;
    const int lane = tid & 31, w = tid >> 5;

    __shared__ float sp[NCOEF][256];
    __shared__ float sc[NCOEF];

    const float* kp = g_K + (size_t)n * DIM;
    const float* vp = g_V + (size_t)n * DIM;

    const float k0 = kp[tid], k1 = kp[tid + 256];
    const float v0 = vp[tid], v1 = vp[tid + 256];

    {
        float p0 = 1.f, p1 = 1.f;
#pragma unroll
        for (int j = 0; j < NMOM; j++) {
            sp[NMOM + j][tid] = p0 + p1;
            sp[j][tid]        = fmaf(p0, v0, p1 * v1);
            p0 *= k0; p1 *= k1;
        }
    }
    __syncthreads();

#pragma unroll
    for (int cc = 0; cc < 4; cc++) {
        const int c = w + cc * 8;
        if (c < NCOEF) {
            float s = 0.f;
#pragma unroll
            for (int q = 0; q < 8; q++) s += sp[c][lane + q * 32];
#pragma unroll
            for (int off = 16; off > 0; off >>= 1)
                s += __shfl_xor_sync(0xFFFFFFFFu, s, off);
            if (lane == 0)
                sc[c] = s * c_invfact[(c < NMOM) ? c : c - NMOM];
        }
    }
    __syncthreads();

    const float* qrow = g_Q + (size_t)n * DIM;
    float c[2], nu[2], de[2];
#pragma unroll
    for (int t = 0; t < 2; t++) {
        c[t]  = qrow[tid + t * 256] * 0.04419417382415922f;
        nu[t] = sc[NMOM - 1];
        de[t] = sc[NCOEF - 1];
    }
#pragma unroll
    for (int j = NMOM - 2; j >= 0; j--) {
        const float cu = sc[j], cd = sc[NMOM + j];
#pragma unroll
        for (int t = 0; t < 2; t++) {
            nu[t] = fmaf(nu[t], c[t], cu);
            de[t] = fmaf(de[t], c[t], cd);
        }
    }
    __half* row = g_Oh + (size_t)n * DIM;
#pragma unroll
    for (int t = 0; t < 2; t++)
        row[tid + t * 256] = __float2half_rn(nu[t] / de[t]);
}

// ---------------------------------------------------------------------------
extern "C" void kernel_launch(void* const* d_in, const int* in_sizes, int n_in,
                              void* d_out, int out_size)
{
    const float* h  = (const float*)d_in[0];
    const float* wq = (const float*)d_in[1];
    const float* wk = (const float*)d_in[2];
    const float* wv = (const float*)d_in[3];
    const float* wo = (const float*)d_in[4];
    float* out = (float*)d_out;

    static int attr_done = 0;
    if (!attr_done) {
        cudaFuncSetAttribute(qkv_gemm, cudaFuncAttributeMaxDynamicSharedMemorySize, 98304);
        cudaFuncSetAttribute(out_gemm, cudaFuncAttributeMaxDynamicSharedMemorySize, 98304);
        attr_done = 1;
    }

    split_kernel<<<2048, 256>>>(h, wq, wk, wv, wo);
    qkv_gemm<<<192, 256, 98304>>>();
    ma_kernel<<<NTOK, 256>>>();
    out_gemm<<<128, 256, 98304>>>(out);
}

// round 14
// speedup vs baseline: 1.0716x; 1.0716x over previous
#include <cuda_runtime.h>
#include <cuda_fp16.h>
#include <cstdint>

#define NTOK 2048
#define DIM  512
#define NMOM 13
#define NCOEF (2*NMOM)

// ---------------- scratch (device globals: allocation-free) ----------------
__device__ __half g_hh [NTOK*DIM];
__device__ __half g_Oh [NTOK*DIM];
__device__ __half g_wqh[DIM*DIM];
__device__ __half g_wkh[DIM*DIM];
__device__ __half g_wvh[DIM*DIM];
__device__ __half g_woh[DIM*DIM];
__device__ float g_Q[NTOK*DIM], g_K[NTOK*DIM], g_V[NTOK*DIM];

// ---------------- PTX helpers ----------------
__device__ __forceinline__ uint32_t smem_u32(const void* p) {
    uint32_t a;
    asm("{ .reg .u64 t; cvta.to.shared.u64 t, %1; cvt.u32.u64 %0, t; }" : "=r"(a) : "l"(p));
    return a;
}
__device__ __forceinline__ void cpa16(uint32_t sdst, const void* gsrc) {
    asm volatile("cp.async.cg.shared.global [%0], [%1], 16;\n" :: "r"(sdst), "l"(gsrc));
}
#define CP_COMMIT() asm volatile("cp.async.commit_group;\n" ::: "memory")
#define CP_WAIT(n)  asm volatile("cp.async.wait_group %0;\n" :: "n"(n) : "memory")

__device__ __forceinline__ void ldsm4(uint32_t* r, uint32_t addr) {
    asm volatile("ldmatrix.sync.aligned.m8n8.x4.shared.b16 {%0,%1,%2,%3}, [%4];"
        : "=r"(r[0]), "=r"(r[1]), "=r"(r[2]), "=r"(r[3]) : "r"(addr));
}
__device__ __forceinline__ void mma_f16(float* c, const uint32_t* a,
                                        uint32_t b0, uint32_t b1) {
    asm volatile(
        "mma.sync.aligned.m16n8k16.row.col.f32.f16.f16.f32 "
        "{%0,%1,%2,%3}, {%4,%5,%6,%7}, {%8,%9}, {%0,%1,%2,%3};"
        : "+f"(c[0]), "+f"(c[1]), "+f"(c[2]), "+f"(c[3])
        : "r"(a[0]), "r"(a[1]), "r"(a[2]), "r"(a[3]), "r"(b0), "r"(b1));
}

// ---------------------------------------------------------------------------
// fp16 GEMM tile, NST-stage cp.async pipeline, NTHR threads, WMSxWNS warps.
// C[m,n] = sum_k A[m,k]*B[n,k];  K = kIters*64.
// ---------------------------------------------------------------------------
template<int BM, int BN, int NTHR>
__device__ __forceinline__ void gemm_fill(uint32_t base,
    const __half* A, const __half* B, int k0, int tid)
{
#pragma unroll
    for (int i = 0; i < BM * 8 / NTHR; i++) {
        const int idx = i * NTHR + tid;
        const int r = idx >> 3, u = idx & 7;
        cpa16(base + r * 128 + ((u ^ (r & 7)) << 4),
              A + (size_t)r * DIM + k0 + u * 8);
    }
#pragma unroll
    for (int i = 0; i < BN * 8 / NTHR; i++) {
        const int idx = i * NTHR + tid;
        const int r = idx >> 3, u = idx & 7;
        cpa16(base + BM * 128 + r * 128 + ((u ^ (r & 7)) << 4),
              B + (size_t)r * DIM + k0 + u * 8);
    }
}

template<int BM, int BN, int NST, int WMS, int WNS, int NTHR>
__device__ void gemm_tile(const __half* __restrict__ A,
                          const __half* __restrict__ B,
                          float* __restrict__ C,
                          int mBase, int nBase, int kIters)
{
    constexpr int WMR = BM / WMS;       // warp m-range
    constexpr int WNR = BN / WNS;       // warp n-range
    constexpr int MT  = WMR / 16;       // a ldsm groups
    constexpr int BT  = WNR / 16;       // b ldsm groups
    constexpr int NTT = WNR / 8;        // 8-wide n subtiles
    constexpr int STG = (BM + BN) * 128;

    extern __shared__ __align__(1024) char smem[];
    const uint32_t sb = smem_u32(smem);
    const int tid = threadIdx.x, lane = tid & 31, wid = tid >> 5;
    const int wm = wid / WNS, wn = wid % WNS;

    const __half* Ab = A + (size_t)mBase * DIM;
    const __half* Bb = B + (size_t)nBase * DIM;

    float acc[MT][NTT][4];
#pragma unroll
    for (int i = 0; i < MT; i++)
#pragma unroll
        for (int j = 0; j < NTT; j++)
#pragma unroll
            for (int q = 0; q < 4; q++) acc[i][j][q] = 0.f;

    // Prologue: fill stages 0..NST-2.
#pragma unroll
    for (int s = 0; s < NST - 1; s++) {
        gemm_fill<BM, BN, NTHR>(sb + s * STG, Ab, Bb, s * 64, tid);
        CP_COMMIT();
    }

    const int lrow = lane & 15, lhi = lane >> 4;

    int stage = 0, fstage = NST - 1;
    for (int it = 0; it < kIters; ++it) {
        CP_WAIT(NST - 2);         // fill(it) complete
        __syncthreads();
        if (it + NST - 1 < kIters)
            gemm_fill<BM, BN, NTHR>(sb + fstage * STG, Ab, Bb, (it + NST - 1) * 64, tid);
        CP_COMMIT();              // possibly-empty group keeps wait count honest

        const uint32_t base = sb + stage * STG;
#pragma unroll
        for (int ks = 0; ks < 4; ks++) {
            const int u = ks * 2 + lhi;
            uint32_t a[MT][4], b[BT][4];
#pragma unroll
            for (int mt = 0; mt < MT; mt++) {
                const int r = wm * WMR + mt * 16 + lrow;
                ldsm4(a[mt], base + r * 128 + ((u ^ (r & 7)) << 4));
            }
#pragma unroll
            for (int bt = 0; bt < BT; bt++) {
                const int r = wn * WNR + bt * 16 + lrow;
                ldsm4(b[bt], base + BM * 128 + r * 128 + ((u ^ (r & 7)) << 4));
            }
#pragma unroll
            for (int mt = 0; mt < MT; mt++)
#pragma unroll
                for (int nt = 0; nt < NTT; nt++) {
                    const uint32_t b0 = (nt & 1) ? b[nt >> 1][1] : b[nt >> 1][0];
                    const uint32_t b1 = (nt & 1) ? b[nt >> 1][3] : b[nt >> 1][2];
                    mma_f16(acc[mt][nt], a[mt], b0, b1);
                }
        }
        stage  = (stage  == NST - 1) ? 0 : stage + 1;
        fstage = (fstage == NST - 1) ? 0 : fstage + 1;
    }

    const int crow = mBase + wm * WMR + (lane >> 2);
    const int ccol = nBase + wn * WNR + (lane & 3) * 2;
#pragma unroll
    for (int mt = 0; mt < MT; mt++)
#pragma unroll
        for (int nt = 0; nt < NTT; nt++) {
            float* p0 = C + (size_t)(crow + mt * 16) * DIM + ccol + nt * 8;
            float* p1 = p0 + 8 * DIM;
            *(float2*)p0 = make_float2(acc[mt][nt][0], acc[mt][nt][1]);
            *(float2*)p1 = make_float2(acc[mt][nt][2], acc[mt][nt][3]);
        }
}

// QKV (R12 config): 384 CTAs (3 x 32 m x 4 n), BM=64 BN=128, 3-stage, occ 3.
__global__ void __launch_bounds__(256, 3)
qkv_gemm()
{
    const int j = blockIdx.x;
    const int which = j >> 7, t = j & 127;
    const __half* B = (which == 0) ? g_wqh : (which == 1) ? g_wkh : g_wvh;
    float*       C  = (which == 0) ? g_Q   : (which == 1) ? g_K   : g_V;
    gemm_tile<64, 128, 3, 2, 4, 256>(g_hh, B, C, (t >> 2) * 64, (t & 3) * 128, 8);
}

// out: 128 CTAs (32 m x 4 n), BM=64 BN=128, 4-stage, 512 threads (16 warps,
// 4x4 warp grid, warp tile 16x32) -> latency covered by warp count.
__global__ void __launch_bounds__(512, 2)
out_gemm(float* __restrict__ out)
{
    const int t = blockIdx.x;
    gemm_tile<64, 128, 4, 4, 4, 512>(g_Oh, g_woh, out, (t >> 2) * 64, (t & 3) * 128, 8);
}

// ---------------- fp32 -> fp16 convert (vectorized) -------------------------
__global__ void __launch_bounds__(256)
split_kernel(const float* __restrict__ h,  const float* __restrict__ wq,
             const float* __restrict__ wk, const float* __restrict__ wv,
             const float* __restrict__ wo)
{
    const int i = blockIdx.x * 256 + threadIdx.x;   // vec4 index
    const float4* src; __half* dst; int off;
    if (i < 262144) { src = (const float4*)h; dst = g_hh; off = i; }
    else {
        const int j = i - 262144;
        const int w = j >> 16;
        off = j & 65535;
        src = (const float4*)((w == 0) ? wq : (w == 1) ? wk : (w == 2) ? wv : wo);
        dst = (w == 0) ? g_wqh : (w == 1) ? g_wkh : (w == 2) ? g_wvh : g_woh;
    }
    const float4 x = src[off];
    __half2* d = (__half2*)(dst + (size_t)off * 4);
    d[0] = __floats2half2_rn(x.x, x.y);
    d[1] = __floats2half2_rn(x.z, x.w);
}

// ---------------------------------------------------------------------------
// Fused moments + apply.  Block per token, 256 threads (8 warps).
// ---------------------------------------------------------------------------
__device__ __constant__ float c_invfact[NMOM] = {
    1.0f, 1.0f, 0.5f, 1.6666667e-1f, 4.1666668e-2f, 8.3333338e-3f,
    1.3888889e-3f, 1.9841270e-4f, 2.4801588e-5f, 2.7557319e-6f,
    2.7557319e-7f, 2.5052108e-8f, 2.0876757e-9f };

__global__ void __launch_bounds__(256)
ma_kernel()
{
    const int n    = blockIdx.x;
    const int tid  = threadIdx.x;
    const int lane = tid & 31, w = tid >> 5;

    __shared__ float sp[NCOEF][256];
    __shared__ float sc[NCOEF];

    const float* kp = g_K + (size_t)n * DIM;
    const float* vp = g_V + (size_t)n * DIM;

    const float k0 = kp[tid], k1 = kp[tid + 256];
    const float v0 = vp[tid], v1 = vp[tid + 256];

    {
        float p0 = 1.f, p1 = 1.f;
#pragma unroll
        for (int j = 0; j < NMOM; j++) {
            sp[NMOM + j][tid] = p0 + p1;
            sp[j][tid]        = fmaf(p0, v0, p1 * v1);
            p0 *= k0; p1 *= k1;
        }
    }
    __syncthreads();

#pragma unroll
    for (int cc = 0; cc < 4; cc++) {
        const int c = w + cc * 8;
        if (c < NCOEF) {
            float s = 0.f;
#pragma unroll
            for (int q = 0; q < 8; q++) s += sp[c][lane + q * 32];
#pragma unroll
            for (int off = 16; off > 0; off >>= 1)
                s += __shfl_xor_sync(0xFFFFFFFFu, s, off);
            if (lane == 0)
                sc[c] = s * c_invfact[(c < NMOM) ? c : c - NMOM];
        }
    }
    __syncthreads();

    const float* qrow = g_Q + (size_t)n * DIM;
    float c[2], nu[2], de[2];
#pragma unroll
    for (int t = 0; t < 2; t++) {
        c[t]  = qrow[tid + t * 256] * 0.04419417382415922f;
        nu[t] = sc[NMOM - 1];
        de[t] = sc[NCOEF - 1];
    }
#pragma unroll
    for (int j = NMOM - 2; j >= 0; j--) {
        const float cu = sc[j], cd = sc[NMOM + j];
#pragma unroll
        for (int t = 0; t < 2; t++) {
            nu[t] = fmaf(nu[t], c[t], cu);
            de[t] = fmaf(de[t], c[t], cd);
        }
    }
    __half* row = g_Oh + (size_t)n * DIM;
#pragma unroll
    for (int t = 0; t < 2; t++)
        row[tid + t * 256] = __float2half_rn(nu[t] / de[t]);
}

// ---------------------------------------------------------------------------
extern "C" void kernel_launch(void* const* d_in, const int* in_sizes, int n_in,
                              void* d_out, int out_size)
{
    const float* h  = (const float*)d_in[0];
    const float* wq = (const float*)d_in[1];
    const float* wk = (const float*)d_in[2];
    const float* wv = (const float*)d_in[3];
    const float* wo = (const float*)d_in[4];
    float* out = (float*)d_out;

    static int attr_done = 0;
    if (!attr_done) {
        cudaFuncSetAttribute(qkv_gemm, cudaFuncAttributeMaxDynamicSharedMemorySize, 73728);
        cudaFuncSetAttribute(out_gemm, cudaFuncAttributeMaxDynamicSharedMemorySize, 98304);
        attr_done = 1;
    }

    split_kernel<<<2048, 256>>>(h, wq, wk, wv, wo);
    qkv_gemm<<<384, 256, 73728>>>();
    ma_kernel<<<NTOK, 256>>>();
    out_gemm<<<128, 512, 98304>>>(out);
}

// round 15
// speedup vs baseline: 1.1156x; 1.0411x over previous
#include <cuda_runtime.h>
#include <cuda_fp16.h>
#include <cstdint>

#define NTOK 2048
#define DIM  512
#define NMOM 13
#define NCOEF (2*NMOM)

// ---------------- scratch (device globals: allocation-free) ----------------
__device__ __half g_hh [NTOK*DIM];
__device__ __half g_Oh [NTOK*DIM];
__device__ __half g_wqh[DIM*DIM];
__device__ __half g_wkh[DIM*DIM];
__device__ __half g_wvh[DIM*DIM];
__device__ __half g_woh[DIM*DIM];
__device__ float g_Q[NTOK*DIM], g_K[NTOK*DIM], g_V[NTOK*DIM];

// ---------------- PTX helpers ----------------
__device__ __forceinline__ uint32_t smem_u32(const void* p) {
    uint32_t a;
    asm("{ .reg .u64 t; cvta.to.shared.u64 t, %1; cvt.u32.u64 %0, t; }" : "=r"(a) : "l"(p));
    return a;
}
__device__ __forceinline__ void cpa16(uint32_t sdst, const void* gsrc) {
    asm volatile("cp.async.cg.shared.global [%0], [%1], 16;\n" :: "r"(sdst), "l"(gsrc));
}
#define CP_COMMIT() asm volatile("cp.async.commit_group;\n" ::: "memory")
#define CP_WAIT(n)  asm volatile("cp.async.wait_group %0;\n" :: "n"(n) : "memory")

__device__ __forceinline__ void ldsm4(uint32_t* r, uint32_t addr) {
    asm volatile("ldmatrix.sync.aligned.m8n8.x4.shared.b16 {%0,%1,%2,%3}, [%4];"
        : "=r"(r[0]), "=r"(r[1]), "=r"(r[2]), "=r"(r[3]) : "r"(addr));
}
__device__ __forceinline__ void mma_f16(float* c, const uint32_t* a,
                                        uint32_t b0, uint32_t b1) {
    asm volatile(
        "mma.sync.aligned.m16n8k16.row.col.f32.f16.f16.f32 "
        "{%0,%1,%2,%3}, {%4,%5,%6,%7}, {%8,%9}, {%0,%1,%2,%3};"
        : "+f"(c[0]), "+f"(c[1]), "+f"(c[2]), "+f"(c[3])
        : "r"(a[0]), "r"(a[1]), "r"(a[2]), "r"(a[3]), "r"(b0), "r"(b1));
}
// fp16 accumulator variant: 2x issue rate on the fallback HMMA path.
__device__ __forceinline__ void mma_f16acc(uint32_t* c, const uint32_t* a,
                                           uint32_t b0, uint32_t b1) {
    asm volatile(
        "mma.sync.aligned.m16n8k16.row.col.f16.f16.f16.f16 "
        "{%0,%1}, {%2,%3,%4,%5}, {%6,%7}, {%0,%1};"
        : "+r"(c[0]), "+r"(c[1])
        : "r"(a[0]), "r"(a[1]), "r"(a[2]), "r"(a[3]), "r"(b0), "r"(b1));
}

// ---------------------------------------------------------------------------
// fp16 GEMM tile, NST-stage cp.async pipeline, 256 threads, 2(m)x4(n) warps.
// HACC: fp16 accumulators (use only where downstream damping tolerates it).
// C[m,n] = sum_k A[m,k]*B[n,k];  K = kIters*64.
// ---------------------------------------------------------------------------
template<int BM, int BN>
__device__ __forceinline__ void gemm_fill(uint32_t base,
    const __half* A, const __half* B, int k0, int tid)
{
#pragma unroll
    for (int i = 0; i < BM / 32; i++) {
        const int idx = i * 256 + tid;
        const int r = idx >> 3, u = idx & 7;
        cpa16(base + r * 128 + ((u ^ (r & 7)) << 4),
              A + (size_t)r * DIM + k0 + u * 8);
    }
#pragma unroll
    for (int i = 0; i < BN / 32; i++) {
        const int idx = i * 256 + tid;
        const int r = idx >> 3, u = idx & 7;
        cpa16(base + BM * 128 + r * 128 + ((u ^ (r & 7)) << 4),
              B + (size_t)r * DIM + k0 + u * 8);
    }
}

template<int BM, int BN, int NST, bool HACC>
__device__ void gemm_tile(const __half* __restrict__ A,
                          const __half* __restrict__ B,
                          float* __restrict__ C,
                          int mBase, int nBase, int kIters)
{
    constexpr int MT  = BM / 32;
    constexpr int BT  = BN / 64;
    constexpr int NTT = BN / 32;
    constexpr int STG = (BM + BN) * 128;

    extern __shared__ __align__(1024) char smem[];
    const uint32_t sb = smem_u32(smem);
    const int tid = threadIdx.x, lane = tid & 31, wid = tid >> 5;
    const int wm = wid >> 2, wn = wid & 3;

    const __half* Ab = A + (size_t)mBase * DIM;
    const __half* Bb = B + (size_t)nBase * DIM;

    float    accf[MT][NTT][4];
    uint32_t acch[MT][NTT][2];
#pragma unroll
    for (int i = 0; i < MT; i++)
#pragma unroll
        for (int j = 0; j < NTT; j++) {
            if (HACC) { acch[i][j][0] = 0u; acch[i][j][1] = 0u; }
            else {
#pragma unroll
                for (int q = 0; q < 4; q++) accf[i][j][q] = 0.f;
            }
        }

    // Prologue: fill stages 0..NST-2.
#pragma unroll
    for (int s = 0; s < NST - 1; s++) {
        gemm_fill<BM, BN>(sb + s * STG, Ab, Bb, s * 64, tid);
        CP_COMMIT();
    }

    const int lrow = lane & 15, lhi = lane >> 4;

    int stage = 0, fstage = NST - 1;
    for (int it = 0; it < kIters; ++it) {
        CP_WAIT(NST - 2);
        __syncthreads();
        if (it + NST - 1 < kIters)
            gemm_fill<BM, BN>(sb + fstage * STG, Ab, Bb, (it + NST - 1) * 64, tid);
        CP_COMMIT();              // possibly-empty group keeps wait count honest

        const uint32_t base = sb + stage * STG;
#pragma unroll
        for (int ks = 0; ks < 4; ks++) {
            const int u = ks * 2 + lhi;
            uint32_t a[MT][4], b[BT][4];
#pragma unroll
            for (int mt = 0; mt < MT; mt++) {
                const int r = wm * (BM / 2) + mt * 16 + lrow;
                ldsm4(a[mt], base + r * 128 + ((u ^ (r & 7)) << 4));
            }
#pragma unroll
            for (int bt = 0; bt < BT; bt++) {
                const int r = wn * (BN / 4) + bt * 16 + lrow;
                ldsm4(b[bt], base + BM * 128 + r * 128 + ((u ^ (r & 7)) << 4));
            }
#pragma unroll
            for (int mt = 0; mt < MT; mt++)
#pragma unroll
                for (int nt = 0; nt < NTT; nt++) {
                    const uint32_t b0 = (nt & 1) ? b[nt >> 1][1] : b[nt >> 1][0];
                    const uint32_t b1 = (nt & 1) ? b[nt >> 1][3] : b[nt >> 1][2];
                    if (HACC) mma_f16acc(acch[mt][nt], a[mt], b0, b1);
                    else      mma_f16(accf[mt][nt], a[mt], b0, b1);
                }
        }
        stage  = (stage  == NST - 1) ? 0 : stage + 1;
        fstage = (fstage == NST - 1) ? 0 : fstage + 1;
    }

    const int crow = mBase + wm * (BM / 2) + (lane >> 2);
    const int ccol = nBase + wn * (BN / 4) + (lane & 3) * 2;
#pragma unroll
    for (int mt = 0; mt < MT; mt++)
#pragma unroll
        for (int nt = 0; nt < NTT; nt++) {
            float* p0 = C + (size_t)(crow + mt * 16) * DIM + ccol + nt * 8;
            float* p1 = p0 + 8 * DIM;
            if (HACC) {
                const __half2 lo = *(const __half2*)&acch[mt][nt][0];
                const __half2 hi = *(const __half2*)&acch[mt][nt][1];
                *(float2*)p0 = make_float2(__half2float(__low2half(lo)),
                                           __half2float(__high2half(lo)));
                *(float2*)p1 = make_float2(__half2float(__low2half(hi)),
                                           __half2float(__high2half(hi)));
            } else {
                *(float2*)p0 = make_float2(accf[mt][nt][0], accf[mt][nt][1]);
                *(float2*)p1 = make_float2(accf[mt][nt][2], accf[mt][nt][3]);
            }
        }
}

// QKV: 384 CTAs (3 x 32 m x 4 n), BM=64 BN=128, 3-stage, occ 3.
// Q and K use fp16 accumulators (softmax-damped); V keeps fp32.
__global__ void __launch_bounds__(256, 3)
qkv_gemm()
{
    const int j = blockIdx.x;
    const int which = j >> 7, t = j & 127;
    const int mB = (t >> 2) * 64, nB = (t & 3) * 128;
    if (which == 0)
        gemm_tile<64, 128, 3, true >(g_hh, g_wqh, g_Q, mB, nB, 8);
    else if (which == 1)
        gemm_tile<64, 128, 3, true >(g_hh, g_wkh, g_K, mB, nB, 8);
    else
        gemm_tile<64, 128, 3, false>(g_hh, g_wvh, g_V, mB, nB, 8);
}

// out: 128 CTAs (32 m x 4 n), BM=64 BN=128, 4-stage, 256 threads (R13-best).
__global__ void __launch_bounds__(256, 2)
out_gemm(float* __restrict__ out)
{
    const int t = blockIdx.x;
    gemm_tile<64, 128, 4, false>(g_Oh, g_woh, out, (t >> 2) * 64, (t & 3) * 128, 8);
}

// ---------------- fp32 -> fp16 convert (vectorized) -------------------------
__global__ void __launch_bounds__(256)
split_kernel(const float* __restrict__ h,  const float* __restrict__ wq,
             const float* __restrict__ wk, const float* __restrict__ wv,
             const float* __restrict__ wo)
{
    const int i = blockIdx.x * 256 + threadIdx.x;   // vec4 index
    const float4* src; __half* dst; int off;
    if (i < 262144) { src = (const float4*)h; dst = g_hh; off = i; }
    else {
        const int j = i - 262144;
        const int w = j >> 16;
        off = j & 65535;
        src = (const float4*)((w == 0) ? wq : (w == 1) ? wk : (w == 2) ? wv : wo);
        dst = (w == 0) ? g_wqh : (w == 1) ? g_wkh : (w == 2) ? g_wvh : g_woh;
    }
    const float4 x = src[off];
    __half2* d = (__half2*)(dst + (size_t)off * 4);
    d[0] = __floats2half2_rn(x.x, x.y);
    d[1] = __floats2half2_rn(x.z, x.w);
}

// ---------------------------------------------------------------------------
// Fused moments + apply.  Block per token, 256 threads (8 warps).
// ---------------------------------------------------------------------------
__device__ __constant__ float c_invfact[NMOM] = {
    1.0f, 1.0f, 0.5f, 1.6666667e-1f, 4.1666668e-2f, 8.3333338e-3f,
    1.3888889e-3f, 1.9841270e-4f, 2.4801588e-5f, 2.7557319e-6f,
    2.7557319e-7f, 2.5052108e-8f, 2.0876757e-9f };

__global__ void __launch_bounds__(256)
ma_kernel()
{
    const int n    = blockIdx.x;
    const int tid  = threadIdx.x;
    const int lane = tid & 31, w = tid >> 5;

    __shared__ float sp[NCOEF][256];
    __shared__ float sc[NCOEF];

    const float* kp = g_K + (size_t)n * DIM;
    const float* vp = g_V + (size_t)n * DIM;

    const float k0 = kp[tid], k1 = kp[tid + 256];
    const float v0 = vp[tid], v1 = vp[tid + 256];

    {
        float p0 = 1.f, p1 = 1.f;
#pragma unroll
        for (int j = 0; j < NMOM; j++) {
            sp[NMOM + j][tid] = p0 + p1;
            sp[j][tid]        = fmaf(p0, v0, p1 * v1);
            p0 *= k0; p1 *= k1;
        }
    }
    __syncthreads();

#pragma unroll
    for (int cc = 0; cc < 4; cc++) {
        const int c = w + cc * 8;
        if (c < NCOEF) {
            float s = 0.f;
#pragma unroll
            for (int q = 0; q < 8; q++) s += sp[c][lane + q * 32];
#pragma unroll
            for (int off = 16; off > 0; off >>= 1)
                s += __shfl_xor_sync(0xFFFFFFFFu, s, off);
            if (lane == 0)
                sc[c] = s * c_invfact[(c < NMOM) ? c : c - NMOM];
        }
    }
    __syncthreads();

    const float* qrow = g_Q + (size_t)n * DIM;
    float c[2], nu[2], de[2];
#pragma unroll
    for (int t = 0; t < 2; t++) {
        c[t]  = qrow[tid + t * 256] * 0.04419417382415922f;
        nu[t] = sc[NMOM - 1];
        de[t] = sc[NCOEF - 1];
    }
#pragma unroll
    for (int j = NMOM - 2; j >= 0; j--) {
        const float cu = sc[j], cd = sc[NMOM + j];
#pragma unroll
        for (int t = 0; t < 2; t++) {
            nu[t] = fmaf(nu[t], c[t], cu);
            de[t] = fmaf(de[t], c[t], cd);
        }
    }
    __half* row = g_Oh + (size_t)n * DIM;
#pragma unroll
    for (int t = 0; t < 2; t++)
        row[tid + t * 256] = __float2half_rn(nu[t] / de[t]);
}

// ---------------------------------------------------------------------------
extern "C" void kernel_launch(void* const* d_in, const int* in_sizes, int n_in,
                              void* d_out, int out_size)
{
    const float* h  = (const float*)d_in[0];
    const float* wq = (const float*)d_in[1];
    const float* wk = (const float*)d_in[2];
    const float* wv = (const float*)d_in[3];
    const float* wo = (const float*)d_in[4];
    float* out = (float*)d_out;

    static int attr_done = 0;
    if (!attr_done) {
        cudaFuncSetAttribute(qkv_gemm, cudaFuncAttributeMaxDynamicSharedMemorySize, 73728);
        cudaFuncSetAttribute(out_gemm, cudaFuncAttributeMaxDynamicSharedMemorySize, 98304);
        attr_done = 1;
    }

    split_kernel<<<2048, 256>>>(h, wq, wk, wv, wo);
    qkv_gemm<<<384, 256, 73728>>>();
    ma_kernel<<<NTOK, 256>>>();
    out_gemm<<<128, 256, 98304>>>(out);
}